// round 2
// baseline (speedup 1.0000x reference)
#include <cuda_runtime.h>
#include <cstdint>

// Problem: RipsH1 — edge-length gather.
//   deaths[i]   = || points[verts0[i,0]] - points[verts0[i,1]] ||      i in [0, E0)
//   dgm1[j,0]   = || points[verts1[j,0]] - points[verts1[j,1]] ||      j in [0, E1)
//   dgm1[j,1]   = || points[verts1[j,2]] - points[verts1[j,3]] ||
// Output layout: [deaths (E0 floats)] ++ [dgm1 row-major (2*E1 floats)].
//
// NOTE: JAX without x64 silently emits int32 for the "int64" randint —
// index buffers are int32 (stub casting table lists int32, not int64).
// points: 65536 x 8 f32 (2 MB -> L2-resident).

static constexpr int DIM_F4 = 2;        // 8 floats = 2 float4
static constexpr int IDX_MASK = 0xFFFF; // N_POINTS = 65536 (power of two)

__device__ __forceinline__ float dist8(const float4* __restrict__ pts,
                                        int ia, int ib) {
    ia &= IDX_MASK;  // exact for valid inputs; guards against OOB gather
    ib &= IDX_MASK;
    const float4 a0 = __ldg(pts + ia * DIM_F4 + 0);
    const float4 a1 = __ldg(pts + ia * DIM_F4 + 1);
    const float4 b0 = __ldg(pts + ib * DIM_F4 + 0);
    const float4 b1 = __ldg(pts + ib * DIM_F4 + 1);
    float dx, s;
    dx = a0.x - b0.x; s  = dx * dx;
    dx = a0.y - b0.y; s  = fmaf(dx, dx, s);
    dx = a0.z - b0.z; s  = fmaf(dx, dx, s);
    dx = a0.w - b0.w; s  = fmaf(dx, dx, s);
    dx = a1.x - b1.x; s  = fmaf(dx, dx, s);
    dx = a1.y - b1.y; s  = fmaf(dx, dx, s);
    dx = a1.z - b1.z; s  = fmaf(dx, dx, s);
    dx = a1.w - b1.w; s  = fmaf(dx, dx, s);
    return sqrtf(s);
}

__global__ __launch_bounds__(256)
void rips_kernel(const float4* __restrict__ pts,
                 const int2* __restrict__ v0,    // E0 rows of 2 i32
                 const int4* __restrict__ v1,    // E1 rows of 4 i32
                 float* __restrict__ out,
                 int e0, int e1) {
    const int i = blockIdx.x * blockDim.x + threadIdx.x;
    if (i < e0) {
        // deaths
        const int2 idx = __ldg(v0 + i);
        out[i] = dist8(pts, idx.x, idx.y);
    } else {
        const int j = i - e0;
        if (j < e1) {
            const int4 idx = __ldg(v1 + j);
            const float dA = dist8(pts, idx.x, idx.y);
            const float dB = dist8(pts, idx.z, idx.w);
            // offset e0 is odd -> 4B-aligned only; scalar stores
            out[e0 + 2 * (long long)j + 0] = dA;
            out[e0 + 2 * (long long)j + 1] = dB;
        }
    }
}

extern "C" void kernel_launch(void* const* d_in, const int* in_sizes, int n_in,
                              void* d_out, int out_size) {
    const float4* pts = (const float4*)d_in[0];
    const int2*   v0  = (const int2*)d_in[1];
    const int4*   v1  = (const int4*)d_in[2];
    float*        out = (float*)d_out;

    const int e0 = in_sizes[1] / 2;   // verts0 element count / 2 per row
    const int e1 = in_sizes[2] / 4;   // verts1 element count / 4 per row

    const int total   = e0 + e1;
    const int threads = 256;
    const int blocks  = (total + threads - 1) / threads;
    rips_kernel<<<blocks, threads>>>(pts, v0, v1, out, e0, e1);
}

// round 3
// speedup vs baseline: 1.2591x; 1.2591x over previous
#include <cuda_runtime.h>
#include <cstdint>

// RipsH1 edge-length gather, pair-cooperative version.
//
// Flat distance list of D = e0 + 2*e1 distances:
//   t <  e0 : indices (ia, ib) = verts0 row t            -> out[t]
//   t >= e0 : q = t - e0; (ia, ib) = ((int2*)verts1)[q]  -> out[t]
// (verts1 row j = [a0, b0, a1, b1]; dgm1[j,p] = ||pts[v1[4j+2p]] - pts[v1[4j+2p+1]]||,
//  and out layout [deaths ++ dgm1-rowmajor] makes out index == t exactly.)
//
// Two lanes per distance: lane h in {0,1} loads float4 half h of each point.
// Both halves of a point share one 32B sector -> the pair's loads coalesce
// into ONE L1 wavefront per point (2 wavefronts/distance vs 4 in the naive
// one-thread-per-distance version, which was L1-bound at 86.9%).

static constexpr int DIM_F4   = 2;      // 8 floats = 2 float4
static constexpr int IDX_MASK = 0xFFFF; // N_POINTS = 65536

__global__ __launch_bounds__(256)
void rips_pair_kernel(const float4* __restrict__ pts,
                      const int2* __restrict__ v0,   // e0 rows of 2 i32
                      const int2* __restrict__ v1p,  // verts1 viewed as 2*e1 int2 pairs
                      float* __restrict__ out,
                      int e0, int total) {           // total = e0 + 2*e1
    const int gtid = blockIdx.x * blockDim.x + threadIdx.x;
    const int t_raw = gtid >> 1;        // distance id
    const int h     = gtid & 1;         // which float4 half this lane owns
    const bool valid = (t_raw < total);
    const int t = valid ? t_raw : (total - 1);   // clamp: keep warp converged for shfl

    int ia, ib;
    if (t < e0) {
        const int2 p = __ldg(v0 + t);
        ia = p.x; ib = p.y;
    } else {
        const int2 p = __ldg(v1p + (t - e0));
        ia = p.x; ib = p.y;
    }
    ia &= IDX_MASK;
    ib &= IDX_MASK;

    const float4 a = __ldg(pts + ia * DIM_F4 + h);
    const float4 b = __ldg(pts + ib * DIM_F4 + h);

    float dx, s;
    dx = a.x - b.x; s = dx * dx;
    dx = a.y - b.y; s = fmaf(dx, dx, s);
    dx = a.z - b.z; s = fmaf(dx, dx, s);
    dx = a.w - b.w; s = fmaf(dx, dx, s);

    s += __shfl_xor_sync(0xFFFFFFFF, s, 1);   // combine the two halves

    if (valid && h == 0)
        out[t] = sqrtf(s);
}

extern "C" void kernel_launch(void* const* d_in, const int* in_sizes, int n_in,
                              void* d_out, int out_size) {
    const float4* pts = (const float4*)d_in[0];
    const int2*   v0  = (const int2*)d_in[1];
    const int2*   v1p = (const int2*)d_in[2];
    float*        out = (float*)d_out;

    const int e0 = in_sizes[1] / 2;          // verts0 rows
    const int e1 = in_sizes[2] / 4;          // verts1 rows
    const int total = e0 + 2 * e1;           // flat distance count

    const long long nthreads = 2LL * total;  // 2 lanes per distance
    const int threads = 256;
    const int blocks  = (int)((nthreads + threads - 1) / threads);
    rips_pair_kernel<<<blocks, threads>>>(pts, v0, v1p, out, e0, total);
}

// round 4
// speedup vs baseline: 1.4143x; 1.1233x over previous
#include <cuda_runtime.h>
#include <cstdint>

// RipsH1 edge-length gather — pair-cooperative + 4x unrolled for MLP.
//
// Flat distance list, D = e0 + 2*e1:
//   t <  e0 : (ia, ib) = verts0 row t
//   t >= e0 : (ia, ib) = ((int2*)verts1)[t - e0]
//   out[t]  = || pts[ia] - pts[ib] ||      (8-dim)
//
// Layout: 2 lanes per distance (lane h in {0,1} owns float4 half h; the two
// 16B loads of one point share a 32B sector -> 1 L1 wavefront per point).
// Each lane-pair processes U=4 distances, index loads + gathers front-batched
// so 8 independent gathers are in flight per thread (covers ~230cyc L2 hits).
// Warp w owns distances [w*64, w*64+64); pair p takes p, p+16, p+32, p+48
// so every LDG stays pair-coalesced across the warp.

static constexpr int DIM_F4   = 2;      // 8 floats = 2 float4
static constexpr int IDX_MASK = 0xFFFF; // N_POINTS = 65536
static constexpr int U        = 4;      // distances per lane-pair
static constexpr int DIST_PER_WARP = 16 * U;  // 64

__global__ __launch_bounds__(256)
void rips_pair_u4_kernel(const float4* __restrict__ pts,
                         const int2* __restrict__ v0,   // e0 rows of 2 i32
                         const int2* __restrict__ v1p,  // verts1 as 2*e1 int2 pairs
                         float* __restrict__ out,
                         int e0, int total) {           // total = e0 + 2*e1
    const int gtid  = blockIdx.x * blockDim.x + threadIdx.x;
    const int warp  = gtid >> 5;
    const int lane  = gtid & 31;
    const int pair  = lane >> 1;   // 0..15
    const int h     = lane & 1;    // float4 half owned by this lane

    const int base = warp * DIST_PER_WARP + pair;

    // ---- phase 1: index loads (batched) ----
    int t[U], ia[U], ib[U];
    bool valid[U];
#pragma unroll
    for (int u = 0; u < U; u++) {
        int tt = base + u * 16;
        valid[u] = (tt < total);
        tt = valid[u] ? tt : (total - 1);      // clamp -> safe, converged
        t[u] = tt;
        int2 p;
        if (tt < e0) p = __ldg(v0 + tt);
        else         p = __ldg(v1p + (tt - e0));
        ia[u] = p.x & IDX_MASK;
        ib[u] = p.y & IDX_MASK;
    }

    // ---- phase 2: gathers (batched; 2*U independent LDG.128 in flight) ----
    float4 a[U], b[U];
#pragma unroll
    for (int u = 0; u < U; u++) {
        a[u] = __ldg(pts + ia[u] * DIM_F4 + h);
        b[u] = __ldg(pts + ib[u] * DIM_F4 + h);
    }

    // ---- phase 3: math + pair-combine + store ----
#pragma unroll
    for (int u = 0; u < U; u++) {
        float dx, s;
        dx = a[u].x - b[u].x; s = dx * dx;
        dx = a[u].y - b[u].y; s = fmaf(dx, dx, s);
        dx = a[u].z - b[u].z; s = fmaf(dx, dx, s);
        dx = a[u].w - b[u].w; s = fmaf(dx, dx, s);
        s += __shfl_xor_sync(0xFFFFFFFF, s, 1);
        if (valid[u] && h == 0)
            out[t[u]] = sqrtf(s);
    }
}

extern "C" void kernel_launch(void* const* d_in, const int* in_sizes, int n_in,
                              void* d_out, int out_size) {
    const float4* pts = (const float4*)d_in[0];
    const int2*   v0  = (const int2*)d_in[1];
    const int2*   v1p = (const int2*)d_in[2];
    float*        out = (float*)d_out;

    const int e0 = in_sizes[1] / 2;          // verts0 rows
    const int e1 = in_sizes[2] / 4;          // verts1 rows
    const int total = e0 + 2 * e1;           // flat distance count

    const int nwarps  = (total + DIST_PER_WARP - 1) / DIST_PER_WARP;
    const int threads = 256;
    const int blocks  = (nwarps * 32 + threads - 1) / threads;
    rips_pair_u4_kernel<<<blocks, threads>>>(pts, v0, v1p, out, e0, total);
}